// round 3
// baseline (speedup 1.0000x reference)
#include <cuda_runtime.h>
#include <cstdint>

// 64 steps of diffusion-advection on a 1024x1024 periodic grid, emitting
// (T, 3, H, W) fp32 RGB. r-channel of frame t == u_{t+1} exactly (clipped),
// so chunks chain through the r channel; no scratch state.
//
// Temporal blocking T_STEPS=4, OHR=2 owned rows/block, full-width rows.
// Single skewed in-place smem buffer (40 KB): at step s, row r sits at slot
// r-s; new row r is written to slot r-s-1. One __syncthreads per row keeps
// reads/writes race-free (within an iteration, read slots and the write slot
// are disjoint).

#define HH 1024
#define WW 1024
#define HW (HH * WW)

#define DT     0.1f
#define ALPHA  0.05f
#define V_X    0.1f
// V_Y == 0 -> du_dy term vanishes.

#define T_STEPS 4
#define OHR     2
#define RR      (OHR + 2 * T_STEPS)   // 10 rows per tile

__global__ __launch_bounds__(256, 4)
void physics_chunk_kernel(const float* __restrict__ u_in,
                          float* __restrict__ frames,   // base of frame t0
                          int steps)                    // 1..T_STEPS
{
    __shared__ float buf[RR * WW];     // 40 KB

    const int c4   = threadIdx.x;      // float4 column 0..255
    const int x0   = c4 << 2;
    const int lane = c4 & 31;
    const int y0   = blockIdx.x * OHR; // owned rows y0, y0+1

    float4* b4 = (float4*)buf;
    const float4* in4 = (const float4*)u_in;

    // Load RR rows (periodic halo) into slots 0..RR-1.
    #pragma unroll
    for (int rr = 0; rr < RR; ++rr) {
        const int gy = (y0 - T_STEPS + rr) & (HH - 1);
        b4[rr * 256 + c4] = __ldcg(&in4[gy * 256 + c4]);
    }

    for (int s = 0; s < steps; ++s) {
        const int rlo = s + 1;
        const int rhi = RR - 2 - s;    // inclusive

        __syncthreads();               // prior step's writes visible

        // At step s, row r lives at slot r-s.
        float4 up = b4[(rlo - 1 - s) * 256 + c4];
        float4 ce = b4[(rlo - s) * 256 + c4];

        for (int r = rlo; r <= rhi; ++r) {
            float4 dn = b4[(r + 1 - s) * 256 + c4];

            float lw = __shfl_up_sync(0xffffffffu, ce.w, 1);
            float rx = __shfl_down_sync(0xffffffffu, ce.x, 1);
            if (lane == 0)  lw = buf[(r - s) * WW + ((x0 - 1) & (WW - 1))];
            if (lane == 31) rx = buf[(r - s) * WW + ((x0 + 4) & (WW - 1))];

            const float uc[4] = {ce.x, ce.y, ce.z, ce.w};
            const float ul[4] = {lw,   ce.x, ce.y, ce.z};
            const float ur[4] = {ce.y, ce.z, ce.w, rx};
            const float uu[4] = {up.x, up.y, up.z, up.w};
            const float ud[4] = {dn.x, dn.y, dn.z, dn.w};

            float4 un;
            float* unp = &un.x;
            #pragma unroll
            for (int i = 0; i < 4; ++i) {
                const float lap   = ul[i] + ur[i] + uu[i] + ud[i] - 4.0f * uc[i];
                const float du_dx = uc[i] - ul[i];
                float v = uc[i] + DT * (ALPHA * lap - V_X * du_dx);
                unp[i] = fminf(fmaxf(v, 0.0f), 1.0f);
            }

            __syncthreads();           // all reads of this iteration done
            b4[(r - s - 1) * 256 + c4] = un;   // skewed in-place write

            if (r >= T_STEPS && r < T_STEPS + OHR) {
                const int gy  = y0 + (r - T_STEPS);
                const int idx = gy * 256 + c4;
                float4* f4 = (float4*)(frames + (size_t)s * 3 * HW);

                float4 gch, bch;
                gch.x = un.x * 0.5f; gch.y = un.y * 0.5f;
                gch.z = un.z * 0.5f; gch.w = un.w * 0.5f;
                bch.x = 1.0f - un.x; bch.y = 1.0f - un.y;
                bch.z = 1.0f - un.z; bch.w = 1.0f - un.w;

                // Only the last step's r channel is re-read (next chunk input).
                if (s == steps - 1) f4[idx] = un;
                else                __stcs(&f4[idx], un);
                __stcs(&f4[idx +     (HW / 4)], gch);
                __stcs(&f4[idx + 2 * (HW / 4)], bch);
            }

            up = ce;
            ce = dn;
        }
    }
}

extern "C" void kernel_launch(void* const* d_in, const int* in_sizes, int n_in,
                              void* d_out, int out_size) {
    const float* init = (const float*)d_in[0];
    float* out = (float*)d_out;

    const int n_frames = out_size / (3 * HW);

    const float* src = init;
    for (int t0 = 0; t0 < n_frames; t0 += T_STEPS) {
        const int steps = (n_frames - t0 < T_STEPS) ? (n_frames - t0) : T_STEPS;
        float* fr = out + (size_t)t0 * 3 * HW;
        physics_chunk_kernel<<<HH / OHR, 256>>>(src, fr, steps);
        src = fr + (size_t)(steps - 1) * 3 * HW;   // r channel of last frame
    }
}

// round 4
// speedup vs baseline: 1.0665x; 1.0665x over previous
#include <cuda_runtime.h>
#include <cstdint>

// 64 steps of diffusion-advection on a 1024x1024 periodic grid, emitting
// (T, 3, H, W) fp32 RGB. r-channel of frame t == u_{t+1} exactly (clipped),
// so chunks chain through the r channel; no scratch state.
//
// Temporal blocking T_STEPS=2, OHR=2 owned rows/block, full-width rows,
// double-buffered smem (48 KB total) -> 4 blocks/SM, grid 512 = one full
// wave. Exactly one __syncthreads per step (plus covering the initial load).

#define HH 1024
#define WW 1024
#define HW (HH * WW)

#define DT     0.1f
#define ALPHA  0.05f
#define V_X    0.1f
// V_Y == 0 -> du_dy term vanishes.

#define T_STEPS 2
#define OHR     2
#define RR      (OHR + 2 * T_STEPS)   // 6 rows per tile

__global__ __launch_bounds__(256, 4)
void physics_chunk_kernel(const float* __restrict__ u_in,
                          float* __restrict__ frames,   // base of frame t0
                          int steps)                    // 1..T_STEPS
{
    __shared__ float buf0[RR * WW];    // 24 KB
    __shared__ float buf1[RR * WW];    // 24 KB

    const int c4   = threadIdx.x;      // float4 column 0..255
    const int x0   = c4 << 2;
    const int lane = c4 & 31;
    const int y0   = blockIdx.x * OHR; // owned rows y0, y0+1

    const float4* in4 = (const float4*)u_in;

    // Load RR rows (periodic halo) into buffer 0.
    #pragma unroll
    for (int rr = 0; rr < RR; ++rr) {
        const int gy = (y0 - T_STEPS + rr) & (HH - 1);
        ((float4*)buf0)[rr * 256 + c4] = __ldcg(&in4[gy * 256 + c4]);
    }

    #pragma unroll
    for (int s = 0; s < T_STEPS; ++s) {
        if (s >= steps) break;
        __syncthreads();               // initial load (s=0) / prior step's stores
        const float*  bo  = (s & 1) ? buf1 : buf0;
        float*        bn  = (s & 1) ? buf0 : buf1;
        const float4* bo4 = (const float4*)bo;
        float4*       bn4 = (float4*)bn;

        const int rlo = s + 1;
        const int rhi = RR - 2 - s;    // inclusive

        float4 up = bo4[(rlo - 1) * 256 + c4];
        float4 ce = bo4[rlo * 256 + c4];

        #pragma unroll
        for (int r = rlo; r <= rhi; ++r) {
            float4 dn = bo4[(r + 1) * 256 + c4];

            float lw = __shfl_up_sync(0xffffffffu, ce.w, 1);
            float rx = __shfl_down_sync(0xffffffffu, ce.x, 1);
            if (lane == 0)  lw = bo[r * WW + ((x0 - 1) & (WW - 1))];
            if (lane == 31) rx = bo[r * WW + ((x0 + 4) & (WW - 1))];

            const float uc[4] = {ce.x, ce.y, ce.z, ce.w};
            const float ul[4] = {lw,   ce.x, ce.y, ce.z};
            const float ur[4] = {ce.y, ce.z, ce.w, rx};
            const float uu[4] = {up.x, up.y, up.z, up.w};
            const float ud[4] = {dn.x, dn.y, dn.z, dn.w};

            float4 un;
            float* unp = &un.x;
            #pragma unroll
            for (int i = 0; i < 4; ++i) {
                const float lap   = ul[i] + ur[i] + uu[i] + ud[i] - 4.0f * uc[i];
                const float du_dx = uc[i] - ul[i];
                float v = uc[i] + DT * (ALPHA * lap - V_X * du_dx);
                unp[i] = fminf(fmaxf(v, 0.0f), 1.0f);
            }

            bn4[r * 256 + c4] = un;

            // Frame output for owned rows
            if (r >= T_STEPS && r < T_STEPS + OHR) {
                const int gy  = y0 + (r - T_STEPS);
                const int idx = gy * 256 + c4;
                float4* f4 = (float4*)(frames + (size_t)s * 3 * HW);

                float4 gch, bch;
                gch.x = un.x * 0.5f; gch.y = un.y * 0.5f;
                gch.z = un.z * 0.5f; gch.w = un.w * 0.5f;
                bch.x = 1.0f - un.x; bch.y = 1.0f - un.y;
                bch.z = 1.0f - un.z; bch.w = 1.0f - un.w;

                // Only the last step's r channel is re-read (next chunk input).
                if (s == steps - 1) f4[idx] = un;
                else                __stcs(&f4[idx], un);
                __stcs(&f4[idx +     (HW / 4)], gch);
                __stcs(&f4[idx + 2 * (HW / 4)], bch);
            }

            up = ce;
            ce = dn;
        }
    }
}

extern "C" void kernel_launch(void* const* d_in, const int* in_sizes, int n_in,
                              void* d_out, int out_size) {
    const float* init = (const float*)d_in[0];
    float* out = (float*)d_out;

    const int n_frames = out_size / (3 * HW);

    const float* src = init;
    for (int t0 = 0; t0 < n_frames; t0 += T_STEPS) {
        const int steps = (n_frames - t0 < T_STEPS) ? (n_frames - t0) : T_STEPS;
        float* fr = out + (size_t)t0 * 3 * HW;
        physics_chunk_kernel<<<HH / OHR, 256>>>(src, fr, steps);
        src = fr + (size_t)(steps - 1) * 3 * HW;   // r channel of last frame
    }
}